// round 5
// baseline (speedup 1.0000x reference)
#include <cuda_runtime.h>
#include <math.h>

// DiceLoss: logits [8,19,512,512] f32, targets [8,512,512] int32 (harness downcasts i64)
#define NC 19
#define HW (512LL * 512LL)

// Scratch: probs_sum[0..18], inter[19..37], cnt[38..56], valid_count[57]
__device__ float g_acc[3 * NC + 1];
__device__ unsigned int g_done;

__global__ __launch_bounds__(128, 8) void dice_fused_kernel(
    const float* __restrict__ logits,
    const int* __restrict__ targets,
    long long npix,
    float* __restrict__ out)
{
    __shared__ float s_inter[NC];
    __shared__ float s_cnt[NC];
    __shared__ float s_psum[NC];
    __shared__ float s_valid;
    __shared__ int   s_last;

    const int tid = threadIdx.x;
    if (tid < NC) { s_inter[tid] = 0.0f; s_cnt[tid] = 0.0f; s_psum[tid] = 0.0f; }
    if (tid == 0) s_valid = 0.0f;
    __syncthreads();

    float acc[NC];
#pragma unroll
    for (int c = 0; c < NC; c++) acc[c] = 0.0f;
    float vcnt = 0.0f;

    const long long stride = (long long)gridDim.x * blockDim.x;

    for (long long p = (long long)blockIdx.x * blockDim.x + tid; p < npix; p += stride) {
        const int t = __ldcs(&targets[p]);
        const long long b  = p >> 18;            // p / HW
        const long long hw = p & (HW - 1);       // p % HW
        const float* __restrict__ base = logits + b * (long long)NC * HW + hw;

        // Stage all 19 channel logits (independent loads -> MLP=19/thread).
        float e[NC];
#pragma unroll
        for (int c = 0; c < NC; c++) e[c] = __ldcs(&base[(long long)c * HW]);

        float s = 0.0f;
#pragma unroll
        for (int c = 0; c < NC; c++) { e[c] = __expf(e[c]); s += e[c]; }

        const bool valid = (unsigned)t < NC;
        // Fold validity into normalization: masked probs everywhere.
        const float inv = valid ? __frcp_rn(s) : 0.0f;

        float gathered = 0.0f;
#pragma unroll
        for (int c = 0; c < NC; c++) {
            const float pr = e[c] * inv;
            acc[c] += pr;
            if (c == t) gathered = pr;
        }
        if (valid) {
            vcnt += 1.0f;
            atomicAdd(&s_inter[t], gathered);
            atomicAdd(&s_cnt[t], 1.0f);
        }
    }

    // Warp-reduce register accumulators, one shared atomic per warp per class.
#pragma unroll
    for (int c = 0; c < NC; c++) {
        float v = acc[c];
#pragma unroll
        for (int o = 16; o > 0; o >>= 1) v += __shfl_xor_sync(0xffffffffu, v, o);
        if ((tid & 31) == 0) atomicAdd(&s_psum[c], v);
    }
    {
        float v = vcnt;
#pragma unroll
        for (int o = 16; o > 0; o >>= 1) v += __shfl_xor_sync(0xffffffffu, v, o);
        if ((tid & 31) == 0) atomicAdd(&s_valid, v);
    }
    __syncthreads();

    // One global atomic per class per block.
    if (tid < NC) {
        atomicAdd(&g_acc[tid],          s_psum[tid]);
        atomicAdd(&g_acc[NC + tid],     s_inter[tid]);
        atomicAdd(&g_acc[2 * NC + tid], s_cnt[tid]);
    }
    if (tid == 0) atomicAdd(&g_acc[3 * NC], s_valid);

    // Last-block-done: finalize + reset scratch for the next (graph-replayed) call.
    __threadfence();
    if (tid == 0) {
        unsigned prev = atomicAdd(&g_done, 1u);
        s_last = (prev == gridDim.x - 1) ? 1 : 0;
    }
    __syncthreads();

    if (s_last) {
        if (tid < 32) {
            float contrib = 0.0f;
            if (tid < NC) {
                // atomic reads bypass potentially-stale L1
                const float psum  = atomicAdd(&g_acc[tid], 0.0f);
                const float inter = atomicAdd(&g_acc[NC + tid], 0.0f);
                const float cnt   = atomicAdd(&g_acc[2 * NC + tid], 0.0f);
                contrib = 1.0f - (2.0f * inter + 1.0f) / (psum + cnt + 1.0f);
            }
#pragma unroll
            for (int o = 16; o > 0; o >>= 1) contrib += __shfl_xor_sync(0xffffffffu, contrib, o);
            if (tid == 0) {
                const float valid = atomicAdd(&g_acc[3 * NC], 0.0f);
                out[0] = (valid > 0.0f) ? (contrib / (float)NC) : 0.0f;
            }
        }
        __syncthreads();
        if (tid < 3 * NC + 1) g_acc[tid] = 0.0f;
        if (tid == 0) g_done = 0u;
    }
}

extern "C" void kernel_launch(void* const* d_in, const int* in_sizes, int n_in,
                              void* d_out, int out_size) {
    const float* logits  = (const float*)d_in[0];
    const int*   targets = (const int*)d_in[1];
    float* out = (float*)d_out;

    const long long npix = (long long)in_sizes[1];   // B*H*W = 2,097,152

    dice_fused_kernel<<<1184, 128>>>(logits, targets, npix, out);
}